// round 14
// baseline (speedup 1.0000x reference)
#include <cuda_runtime.h>
#include <cuda_bf16.h>
#include <cstdint>

#define S_LEN 4096
#define E_DIM 256
#define HH 256
#define G4 1024      // 4*HH
#define T_TAGS 9
#define START_TAG 7
#define STOP_TAG 8
#define NEG_VAL -10000.0f
#define NCHUNK 64
#define CLEN 64

typedef unsigned long long ull;

// ---------------- device scratch (no allocations allowed) ----------------
__device__ float g_xg[2][S_LEN][G4];     // 32 MB: precomputed x@w_ih.T + b_ih + b_hh
__device__ float g_lstm[S_LEN][2 * HH];  // 8 MB: concat(hf, hb)
__device__ float g_frames[S_LEN][T_TAGS];
__device__ float g_chunkM[NCHUNK][9][9];
__device__ float g_balpha[NCHUNK][16];
__device__ unsigned char g_bp[S_LEN][9];
__device__ unsigned char g_exitmap[NCHUNK][16];
__device__ int g_best;

// =========================================================================
// Kernel 1: x_gates GEMM with embedding gather. (R12 verbatim)
// =========================================================================
__global__ void xgates_kernel(const int* __restrict__ sentence,
                              const float* __restrict__ embed,
                              const float* __restrict__ w_ih_f,
                              const float* __restrict__ b_ih_f,
                              const float* __restrict__ b_hh_f,
                              const float* __restrict__ w_ih_b,
                              const float* __restrict__ b_ih_b,
                              const float* __restrict__ b_hh_b)
{
    __shared__ float s_x[64][65];
    __shared__ float s_w[64][65];
    __shared__ int   s_sent[64];

    int t  = threadIdx.x;            // 256 threads
    int tx = t & 15, ty = t >> 4;
    int bx = blockIdx.x;             // position tile (64 positions)
    int by = blockIdx.y;             // row tile (64 gate rows)

    if (t < 64) s_sent[t] = sentence[bx * 64 + t];
    __syncthreads();

    float acc[4][4] = {};

    for (int kc = 0; kc < 4; kc++) {
        int k0 = kc * 64;
        #pragma unroll
        for (int qq = 0; qq < 16; qq++) {
            int idx = t + 256 * qq;
            int i = idx >> 6, kk = idx & 63;
            s_x[i][kk] = embed[(long)s_sent[i] * E_DIM + k0 + kk];
        }
        #pragma unroll
        for (int qq = 0; qq < 16; qq++) {
            int idx = t + 256 * qq;
            int i = idx >> 6, kk = idx & 63;
            int R = by * 64 + i;
            const float* w = (R < 1024) ? w_ih_f : w_ih_b;
            int r = R & 1023;
            s_w[i][kk] = w[r * E_DIM + k0 + kk];
        }
        __syncthreads();
        #pragma unroll
        for (int kk = 0; kk < 64; kk++) {
            float a[4], b[4];
            #pragma unroll
            for (int i = 0; i < 4; i++) a[i] = s_w[ty * 4 + i][kk];
            #pragma unroll
            for (int j = 0; j < 4; j++) b[j] = s_x[tx * 4 + j][kk];
            #pragma unroll
            for (int i = 0; i < 4; i++)
                #pragma unroll
                for (int j = 0; j < 4; j++)
                    acc[i][j] += a[i] * b[j];
        }
        __syncthreads();
    }

    #pragma unroll
    for (int i = 0; i < 4; i++) {
        int R = by * 64 + ty * 4 + i;
        int dir = R >> 10;
        int r = R & 1023;
        float bias = dir ? (b_ih_b[r] + b_hh_b[r]) : (b_ih_f[r] + b_hh_f[r]);
        #pragma unroll
        for (int j = 0; j < 4; j++) {
            int p = bx * 64 + tx * 4 + j;
            g_xg[dir][p][r] = acc[i][j] + bias;
        }
    }
}

// ---------------- shared helpers ----------------
__device__ __forceinline__ uint32_t smem_u32(const void* p) {
    return (uint32_t)__cvta_generic_to_shared(p);
}
__device__ __forceinline__ ull fma2(ull a, ull b, ull c) {
    asm("fma.rn.f32x2 %0, %1, %2, %0;" : "+l"(c) : "l"(a), "l"(b));
    return c;
}
__device__ __forceinline__ float sum2(ull a) {
    float lo, hi;
    asm("mov.b64 {%0,%1}, %2;" : "=f"(lo), "=f"(hi) : "l"(a));
    return lo + hi;
}
__device__ __forceinline__ float fsig(float x) {
    return __fdividef(1.f, 1.f + __expf(-x));
}
__device__ __forceinline__ float ftanh(float x) {
    x = fminf(fmaxf(x, -15.f), 15.f);
    float e = __expf(2.f * x);
    return __fdividef(e - 1.f, e + 1.f);
}
__device__ __forceinline__ void mbar_wait_cluster(uint32_t mb, uint32_t parity) {
    uint32_t done;
    asm volatile(
        "{\n\t.reg .pred p;\n\t"
        "mbarrier.try_wait.parity.acquire.cluster.shared::cta.b64 p, [%1], %2;\n\t"
        "selp.b32 %0, 1, 0, p;\n\t}"
        : "=r"(done) : "r"(mb), "r"(parity) : "memory");
    if (!done) {
        asm volatile(
            "{\n\t.reg .pred P1;\n\t"
            "WL_%=:\n\t"
            "mbarrier.try_wait.parity.acquire.cluster.shared::cta.b64 P1, [%0], %1, 0x989680;\n\t"
            "@P1 bra.uni WD_%=;\n\t"
            "bra.uni WL_%=;\n\t"
            "WD_%=:\n\t}"
            :: "r"(mb), "r"(parity) : "memory");
    }
}

#define TX_BYTES 1024u  // 8 ranks * 32 units * 4 bytes per phase

// =========================================================================
// Kernel 2: serial recurrence. R12 base + depth-2 xg prefetch (the ONLY
// change vs R12 anywhere in this file).
// =========================================================================
__global__ void __cluster_dims__(8, 1, 1) __launch_bounds__(512, 1)
lstm_kernel(const float* __restrict__ w_hh_f,
            const float* __restrict__ w_hh_b,
            const float* __restrict__ h0,
            const float* __restrict__ c0)
{
    __shared__ __align__(16) float sh_h[2][HH];
    __shared__ __align__(16) float sh_part[128][4];   // [row_local][chunk]
    __shared__ __align__(8) ull mbars[2];

    int t = threadIdx.x;
    int w = t >> 5, l = t & 31;
    int chunk = w & 3;                         // 0..3 -> cols [chunk*64, +64)
    int row_local = ((w >> 2) << 5) + l;       // 0..127
    int dir = blockIdx.x >> 3;
    uint32_t rank;
    asm("mov.u32 %0, %%cluster_ctarank;" : "=r"(rank));
    int q = row_local >> 5;                    // gate: 0=i,1=f,2=g,3=o
    int unit = row_local & 31;
    int row_global = q * HH + (int)rank * 32 + unit;

    const float* whh = dir ? w_hh_b : w_hh_f;
    ulonglong2 wreg[16];
    {
        const ulonglong2* wp = (const ulonglong2*)(whh + row_global * HH + chunk * 64);
        #pragma unroll
        for (int i = 0; i < 16; i++) wreg[i] = wp[i];
    }

    if (t < HH) sh_h[0][t] = h0[dir * HH + t];
    float c = 0.f;
    if (w == 0) c = c0[dir * HH + (int)rank * 32 + l];

    uint32_t mb_local0 = smem_u32(&mbars[0]);
    uint32_t mb_local1 = smem_u32(&mbars[1]);
    if (t == 0) {
        asm volatile("mbarrier.init.shared.b64 [%0], 1;" :: "r"(mb_local0) : "memory");
        asm volatile("mbarrier.init.shared.b64 [%0], 1;" :: "r"(mb_local1) : "memory");
        asm volatile("mbarrier.arrive.expect_tx.shared.b64 _, [%0], %1;" :: "r"(mb_local0), "r"(TX_BYTES) : "memory");
        asm volatile("mbarrier.arrive.expect_tx.shared.b64 _, [%0], %1;" :: "r"(mb_local1), "r"(TX_BYTES) : "memory");
    }

    const float* xg = &g_xg[dir][0][0];
    int s  = dir ? (S_LEN - 1) : 0;
    int ds = dir ? -1 : 1;

    // depth-2 xg prefetch: A = step s, B = step s+1
    float xa0 = 0.f, xa1 = 0.f, xa2 = 0.f, xa3 = 0.f;
    float xb0 = 0.f, xb1 = 0.f, xb2 = 0.f, xb3 = 0.f;
    if (w == 0) {
        const float* xp = xg + s * G4 + (int)rank * 32 + l;
        xa0 = xp[0]; xa1 = xp[HH]; xa2 = xp[2 * HH]; xa3 = xp[3 * HH];
        int s1 = min(max(s + ds, 0), S_LEN - 1);
        const float* xq = xg + s1 * G4 + (int)rank * 32 + l;
        xb0 = xq[0]; xb1 = xq[HH]; xb2 = xq[2 * HH]; xb3 = xq[3 * HH];
    }

    uint32_t rh0[8];
    uint32_t dmb = 0;
    if (w == 0) {
        uint32_t la_h = smem_u32(&sh_h[0][(int)rank * 32 + l]);
        dmb = mb_local0 - la_h;
        #pragma unroll
        for (int p = 0; p < 8; p++)
            asm("mapa.shared::cluster.u32 %0, %1, %2;" : "=r"(rh0[p]) : "r"(la_h), "r"(p));
    }

    __syncthreads();
    asm volatile("barrier.cluster.arrive.aligned;" ::: "memory");
    asm volatile("barrier.cluster.wait.aligned;" ::: "memory");

    float* lstm_ptr = &g_lstm[s][dir * HH + (int)rank * 32 + l];
    long lstm_stride = (long)ds * (2 * HH);
    uint32_t par0 = 0, par1 = 0;

    for (int step = 0; step < S_LEN; step++) {
        int buf = step & 1;
        if (step > 0) {
            if (buf) { mbar_wait_cluster(mb_local1, par1); par1 ^= 1; }
            else     { mbar_wait_cluster(mb_local0, par0); par0 ^= 1; }
        }

        // ---- stage 1: partial dot over this thread's 64 columns (f32x2) ----
        {
            const ulonglong2* hp = (const ulonglong2*)(&sh_h[buf][chunk * 64]);
            ull a0 = 0, a1 = 0, a2 = 0, a3 = 0, a4 = 0, a5 = 0, a6 = 0, a7 = 0;
            #pragma unroll
            for (int i = 0; i < 16; i += 4) {
                ulonglong2 h0v = hp[i + 0], h1v = hp[i + 1], h2v = hp[i + 2], h3v = hp[i + 3];
                a0 = fma2(wreg[i + 0].x, h0v.x, a0);
                a1 = fma2(wreg[i + 0].y, h0v.y, a1);
                a2 = fma2(wreg[i + 1].x, h1v.x, a2);
                a3 = fma2(wreg[i + 1].y, h1v.y, a3);
                a4 = fma2(wreg[i + 2].x, h2v.x, a4);
                a5 = fma2(wreg[i + 2].y, h2v.y, a5);
                a6 = fma2(wreg[i + 3].x, h3v.x, a6);
                a7 = fma2(wreg[i + 3].y, h3v.y, a7);
            }
            float r = ((sum2(a0) + sum2(a1)) + (sum2(a2) + sum2(a3)))
                    + ((sum2(a4) + sum2(a5)) + (sum2(a6) + sum2(a7)));
            sh_part[row_local][chunk] = r;
        }
        __syncthreads();   // sh_part ready; also: all warps passed this step's wait

        // re-arm this step's barrier for its next phase (step+2); off the
        // math chain. Safe: peers' next-phase st.asyncs require our current
        // broadcast below (warp0 program order) — >=1 full flight later.
        if (t == 0 && step > 0) {
            uint32_t mb = buf ? mb_local1 : mb_local0;
            asm volatile("mbarrier.arrive.expect_tx.shared.b64 _, [%0], %1;" :: "r"(mb), "r"(TX_BYTES) : "memory");
        }

        // ---- stage 2: warp0 epilogue — broadcast ASAP, bookkeeping after ----
        if (w == 0) {
            float4 pi = *(const float4*)&sh_part[0 * 32 + l][0];
            float4 pf = *(const float4*)&sh_part[1 * 32 + l][0];
            float4 pg = *(const float4*)&sh_part[2 * 32 + l][0];
            float4 po = *(const float4*)&sh_part[3 * 32 + l][0];

            float gi = xa0 + (pi.x + pi.y) + (pi.z + pi.w);
            float gf = xa1 + (pf.x + pf.y) + (pf.z + pf.w);
            float gg = xa2 + (pg.x + pg.y) + (pg.z + pg.w);
            float go = xa3 + (po.x + po.y) + (po.z + po.w);

            float iv = fsig(gi);
            float fv = fsig(gf);
            float gv = ftanh(gg);
            float ov = fsig(go);

            c = fv * c + iv * gv;
            float hn = ov * ftanh(c);

            // broadcast h(step+1) immediately: data store carries tx signal
            uint32_t hoff = (uint32_t)(buf ^ 1) * (HH * 4);
            uint32_t moff = dmb + (uint32_t)(buf ^ 1) * 8;
            uint32_t hv = __float_as_uint(hn);
            #pragma unroll
            for (int peer = 0; peer < 8; peer++) {
                asm volatile(
                    "st.async.shared::cluster.mbarrier::complete_tx::bytes.b32 [%0], %1, [%2];"
                    :: "r"(rh0[peer] + hoff), "r"(hv), "r"(rh0[peer] + moff) : "memory");
            }

            // off-critical-path bookkeeping: global store + depth-2 prefetch
            *lstm_ptr = hn;
            lstm_ptr += lstm_stride;
            xa0 = xb0; xa1 = xb1; xa2 = xb2; xa3 = xb3;
            int s2 = min(max(s + 2 * ds, 0), S_LEN - 1);
            const float* xp = xg + s2 * G4 + (int)rank * 32 + l;
            xb0 = xp[0]; xb1 = xp[HH]; xb2 = xp[2 * HH]; xb3 = xp[3 * HH];
        }
        s += ds;
    }

    asm volatile("barrier.cluster.arrive.aligned;" ::: "memory");
    asm volatile("barrier.cluster.wait.aligned;" ::: "memory");
}

// =========================================================================
// Kernel 3: emission scores (unchanged)
// =========================================================================
__global__ void frames_kernel(const float* __restrict__ W_out,
                              const float* __restrict__ b_out)
{
    __shared__ float row[512];
    int s = blockIdx.x;
    int t = threadIdx.x;
    row[t] = g_lstm[s][t];
    __syncthreads();
    int wq = t >> 5, l = t & 31;
    if (wq < T_TAGS) {
        float p = 0.f;
        #pragma unroll
        for (int i = 0; i < 16; i++)
            p += row[l + 32 * i] * W_out[wq * 512 + l + 32 * i];
        #pragma unroll
        for (int o = 16; o > 0; o >>= 1)
            p += __shfl_down_sync(0xffffffffu, p, o);
        if (l == 0) g_frames[s][wq] = p + b_out[wq];
    }
}

// =========================================================================
// CRF blocked parallel scan (R12, unchanged)
// =========================================================================
__global__ void crfA_kernel(const float* __restrict__ transitions)
{
    __shared__ float fr[CLEN][9];
    __shared__ float trs[81];
    __shared__ float M[2][9][12];
    int k = blockIdx.x, t = threadIdx.x;   // 96 threads
    for (int i = t; i < CLEN * 9; i += 96)
        fr[i / 9][i % 9] = g_frames[k * CLEN + i / 9][i % 9];
    if (t < 81) trs[t] = transitions[t];
    int e = t / 9, j = t % 9;
    bool act = (t < 81);
    if (act) M[0][e][j] = (e == j) ? 0.f : NEG_VAL;
    __syncthreads();

    float trj[9];
    if (act) {
        #pragma unroll
        for (int i = 0; i < 9; i++) trj[i] = trs[i * 9 + j];
    }
    int cur = 0;
    for (int s = 0; s < CLEN; s++) {
        if (act) {
            float v[9];
            float best = -3.4e38f;
            #pragma unroll
            for (int i = 0; i < 9; i++) {
                v[i] = M[cur][e][i] + trj[i];
                best = fmaxf(best, v[i]);
            }
            float sum = 0.f;
            #pragma unroll
            for (int i = 0; i < 9; i++) sum += __expf(v[i] - best);
            M[cur ^ 1][e][j] = best + __logf(sum) + fr[s][j];
        }
        __syncthreads();
        cur ^= 1;
    }
    if (act) g_chunkM[k][e][j] = M[cur][e][j];
}

__global__ void crfB_kernel(const float* __restrict__ transitions,
                            float* __restrict__ out)
{
    __shared__ float Ms[NCHUNK][9][9];
    __shared__ float alp[16];
    __shared__ float fin[16];
    int t = threadIdx.x;                    // 32 threads
    for (int i = t; i < NCHUNK * 81; i += 32)
        ((float*)Ms)[i] = ((const float*)g_chunkM)[i];
    if (t < 9) alp[t] = (t == START_TAG) ? 0.f : NEG_VAL;
    __syncthreads();

    if (t < 9) {
        int j = t;
        for (int k = 0; k < NCHUNK; k++) {
            g_balpha[k][j] = alp[j];
            float v[9];
            float best = -3.4e38f;
            #pragma unroll
            for (int e = 0; e < 9; e++) {
                v[e] = alp[e] + Ms[k][e][j];
                best = fmaxf(best, v[e]);
            }
            float sum = 0.f;
            #pragma unroll
            for (int e = 0; e < 9; e++) sum += __expf(v[e] - best);
            float na = best + __logf(sum);
            __syncwarp(0x1ffu);
            alp[j] = na;
            __syncwarp(0x1ffu);
        }
        fin[j] = alp[j] + transitions[j * 9 + STOP_TAG];
    }
    __syncthreads();
    if (t == 0) {
        float m = -3.4e38f; int bestj = 0;
        for (int k = 0; k < 9; k++) if (fin[k] > m) { m = fin[k]; bestj = k; }
        float sum = 0.f;
        for (int k = 0; k < 9; k++) sum += __expf(fin[k] - m);
        out[0] = m + __logf(sum);
        g_best = bestj;
    }
}

__global__ void crfC_kernel(const float* __restrict__ transitions)
{
    __shared__ float fr[CLEN][9];
    __shared__ float trs[81];
    __shared__ float alp[16];
    __shared__ unsigned char bps[CLEN][9];
    int k = blockIdx.x, t = threadIdx.x;    // 32 threads
    for (int i = t; i < CLEN * 9; i += 32)
        fr[i / 9][i % 9] = g_frames[k * CLEN + i / 9][i % 9];
    for (int i = t; i < 81; i += 32) trs[i] = transitions[i];
    if (t < 9) alp[t] = g_balpha[k][t];
    __syncthreads();

    if (t < 9) {
        int j = t;
        float trj[9];
        #pragma unroll
        for (int i = 0; i < 9; i++) trj[i] = trs[i * 9 + j];
        int base = k * CLEN;
        for (int s = 0; s < CLEN; s++) {
            float v[9];
            float best = -3.4e38f; int b = 0;
            #pragma unroll
            for (int i = 0; i < 9; i++) {
                float x = alp[i] + trj[i];
                v[i] = x;
                if (x > best) { best = x; b = i; }
            }
            float sum = 0.f;
            #pragma unroll
            for (int i = 0; i < 9; i++) sum += __expf(v[i] - best);
            float na = best + __logf(sum) + fr[s][j];
            bps[s][j] = (unsigned char)b;
            g_bp[base + s][j] = (unsigned char)b;
            __syncwarp(0x1ffu);
            alp[j] = na;
            __syncwarp(0x1ffu);
        }
    }
    __syncthreads();
    if (t < 9) {
        int tg = t;
        int smin = (k == 0) ? 1 : 0;
        for (int s = CLEN - 1; s >= smin; s--) tg = bps[s][tg];
        g_exitmap[k][t] = (unsigned char)tg;
    }
}

// merged E+F: each block composes exit-maps down to its chunk, then backtracks
__global__ void crfEF_kernel(float* __restrict__ out)
{
    __shared__ unsigned char em[NCHUNK][16];
    __shared__ unsigned char bps[CLEN][9];
    int k = blockIdx.x, t = threadIdx.x;     // 64 threads
    for (int i = t; i < NCHUNK * 9; i += 64)
        em[i / 9][i % 9] = g_exitmap[i / 9][i % 9];
    for (int i = t; i < CLEN * 9; i += 64)
        bps[i / 9][i % 9] = g_bp[k * CLEN + i / 9][i % 9];
    __syncthreads();
    if (t == 0) {
        int tg = g_best;
        for (int j = NCHUNK - 1; j > k; j--) tg = em[j][tg];
        int base = k * CLEN;
        out[base + CLEN] = (float)tg;          // out[1 + base + CLEN-1]
        int smin = (k == 0) ? 1 : 0;
        for (int s = CLEN - 1; s >= smin; s--) {
            tg = bps[s][tg];
            out[base + s] = (float)tg;         // out[1 + base + s - 1]
        }
    }
}

// =========================================================================
extern "C" void kernel_launch(void* const* d_in, const int* in_sizes, int n_in,
                              void* d_out, int out_size)
{
    const int*   sentence    = (const int*)d_in[0];
    const float* embed       = (const float*)d_in[1];
    const float* w_ih_f      = (const float*)d_in[2];
    const float* w_hh_f      = (const float*)d_in[3];
    const float* b_ih_f      = (const float*)d_in[4];
    const float* b_hh_f      = (const float*)d_in[5];
    const float* w_ih_b      = (const float*)d_in[6];
    const float* w_hh_b      = (const float*)d_in[7];
    const float* b_ih_b      = (const float*)d_in[8];
    const float* b_hh_b      = (const float*)d_in[9];
    const float* h0          = (const float*)d_in[10];
    const float* c0          = (const float*)d_in[11];
    const float* W_out       = (const float*)d_in[12];
    const float* b_out       = (const float*)d_in[13];
    const float* transitions = (const float*)d_in[14];
    float* out = (float*)d_out;

    dim3 g1(64, 32);
    xgates_kernel<<<g1, 256>>>(sentence, embed, w_ih_f, b_ih_f, b_hh_f,
                               w_ih_b, b_ih_b, b_hh_b);

    lstm_kernel<<<16, 512>>>(w_hh_f, w_hh_b, h0, c0);

    frames_kernel<<<S_LEN, 512>>>(W_out, b_out);

    crfA_kernel<<<NCHUNK, 96>>>(transitions);
    crfB_kernel<<<1, 32>>>(transitions, out);
    crfC_kernel<<<NCHUNK, 32>>>(transitions);
    crfEF_kernel<<<NCHUNK, 64>>>(out);
}

// round 15
// speedup vs baseline: 1.0103x; 1.0103x over previous
#include <cuda_runtime.h>
#include <cuda_bf16.h>
#include <cstdint>

#define S_LEN 4096
#define E_DIM 256
#define HH 256
#define G4 1024      // 4*HH
#define T_TAGS 9
#define START_TAG 7
#define STOP_TAG 8
#define NEG_VAL -10000.0f
#define NCHUNK 64
#define CLEN 64

typedef unsigned long long ull;

// ---------------- device scratch (no allocations allowed) ----------------
__device__ float g_xg[2][S_LEN][G4];     // 32 MB: precomputed x@w_ih.T + b_ih + b_hh
__device__ float g_lstm[S_LEN][2 * HH];  // 8 MB: concat(hf, hb)
__device__ float g_frames[S_LEN][T_TAGS];
__device__ float g_chunkM[NCHUNK][9][9];
__device__ float g_balpha[NCHUNK][16];
__device__ unsigned char g_bp[S_LEN][9];
__device__ unsigned char g_exitmap[NCHUNK][16];
__device__ int g_best;

// =========================================================================
// Kernel 1: x_gates GEMM, smem transposed to [kk][row/pos] (stride 68,
// 16B-aligned): inner loop = 2x LDS.128 + 16 FFMA. Summation order == R12.
// =========================================================================
__global__ void xgates_kernel(const int* __restrict__ sentence,
                              const float* __restrict__ embed,
                              const float* __restrict__ w_ih_f,
                              const float* __restrict__ b_ih_f,
                              const float* __restrict__ b_hh_f,
                              const float* __restrict__ w_ih_b,
                              const float* __restrict__ b_ih_b,
                              const float* __restrict__ b_hh_b)
{
    __shared__ __align__(16) float s_x[64][68];   // [kk][pos]
    __shared__ __align__(16) float s_w[64][68];   // [kk][row]
    __shared__ int   s_sent[64];

    int t  = threadIdx.x;            // 256 threads
    int tx = t & 15, ty = t >> 4;
    int bx = blockIdx.x;             // position tile (64 positions)
    int by = blockIdx.y;             // row tile (64 gate rows)

    if (t < 64) s_sent[t] = sentence[bx * 64 + t];
    __syncthreads();

    float acc[4][4] = {};

    for (int kc = 0; kc < 4; kc++) {
        int k0 = kc * 64;
        #pragma unroll
        for (int qq = 0; qq < 16; qq++) {
            int idx = t + 256 * qq;
            int i = idx >> 6, kk = idx & 63;
            s_x[kk][i] = embed[(long)s_sent[i] * E_DIM + k0 + kk];
        }
        #pragma unroll
        for (int qq = 0; qq < 16; qq++) {
            int idx = t + 256 * qq;
            int i = idx >> 6, kk = idx & 63;
            int R = by * 64 + i;
            const float* w = (R < 1024) ? w_ih_f : w_ih_b;
            int r = R & 1023;
            s_w[kk][i] = w[r * E_DIM + k0 + kk];
        }
        __syncthreads();
        #pragma unroll
        for (int kk = 0; kk < 64; kk++) {
            float4 av = *(const float4*)&s_w[kk][ty * 4];
            float4 bv = *(const float4*)&s_x[kk][tx * 4];
            float a[4] = {av.x, av.y, av.z, av.w};
            float b[4] = {bv.x, bv.y, bv.z, bv.w};
            #pragma unroll
            for (int i = 0; i < 4; i++)
                #pragma unroll
                for (int j = 0; j < 4; j++)
                    acc[i][j] += a[i] * b[j];
        }
        __syncthreads();
    }

    #pragma unroll
    for (int i = 0; i < 4; i++) {
        int R = by * 64 + ty * 4 + i;
        int dir = R >> 10;
        int r = R & 1023;
        float bias = dir ? (b_ih_b[r] + b_hh_b[r]) : (b_ih_f[r] + b_hh_f[r]);
        #pragma unroll
        for (int j = 0; j < 4; j++) {
            int p = bx * 64 + tx * 4 + j;
            g_xg[dir][p][r] = acc[i][j] + bias;
        }
    }
}

// ---------------- shared helpers ----------------
__device__ __forceinline__ uint32_t smem_u32(const void* p) {
    return (uint32_t)__cvta_generic_to_shared(p);
}
__device__ __forceinline__ ull fma2(ull a, ull b, ull c) {
    asm("fma.rn.f32x2 %0, %1, %2, %0;" : "+l"(c) : "l"(a), "l"(b));
    return c;
}
__device__ __forceinline__ float sum2(ull a) {
    float lo, hi;
    asm("mov.b64 {%0,%1}, %2;" : "=f"(lo), "=f"(hi) : "l"(a));
    return lo + hi;
}
__device__ __forceinline__ float fsig(float x) {
    return __fdividef(1.f, 1.f + __expf(-x));
}
__device__ __forceinline__ float ftanh(float x) {
    x = fminf(fmaxf(x, -15.f), 15.f);
    float e = __expf(2.f * x);
    return __fdividef(e - 1.f, e + 1.f);
}
__device__ __forceinline__ void mbar_wait_cluster(uint32_t mb, uint32_t parity) {
    uint32_t done;
    asm volatile(
        "{\n\t.reg .pred p;\n\t"
        "mbarrier.try_wait.parity.acquire.cluster.shared::cta.b64 p, [%1], %2;\n\t"
        "selp.b32 %0, 1, 0, p;\n\t}"
        : "=r"(done) : "r"(mb), "r"(parity) : "memory");
    if (!done) {
        asm volatile(
            "{\n\t.reg .pred P1;\n\t"
            "WL_%=:\n\t"
            "mbarrier.try_wait.parity.acquire.cluster.shared::cta.b64 P1, [%0], %1, 0x989680;\n\t"
            "@P1 bra.uni WD_%=;\n\t"
            "bra.uni WL_%=;\n\t"
            "WD_%=:\n\t}"
            :: "r"(mb), "r"(parity) : "memory");
    }
}

#define TX_BYTES 1024u  // 8 ranks * 32 units * 4 bytes per phase

// =========================================================================
// Kernel 2: serial recurrence. R12 base with warp-0 stream minimized:
// - g_lstm store moved to warp 1 (lag-1 from sh_h; final step post-loop)
// - prefetch bounds check removed (OOB lands in valid g_xg memory, unused)
// =========================================================================
__global__ void __cluster_dims__(8, 1, 1) __launch_bounds__(512, 1)
lstm_kernel(const float* __restrict__ w_hh_f,
            const float* __restrict__ w_hh_b,
            const float* __restrict__ h0,
            const float* __restrict__ c0)
{
    __shared__ __align__(16) float sh_h[2][HH];
    __shared__ __align__(16) float sh_part[128][4];   // [row_local][chunk]
    __shared__ __align__(8) ull mbars[2];

    int t = threadIdx.x;
    int w = t >> 5, l = t & 31;
    int chunk = w & 3;                         // 0..3 -> cols [chunk*64, +64)
    int row_local = ((w >> 2) << 5) + l;       // 0..127
    int dir = blockIdx.x >> 3;
    uint32_t rank;
    asm("mov.u32 %0, %%cluster_ctarank;" : "=r"(rank));
    int q = row_local >> 5;                    // gate: 0=i,1=f,2=g,3=o
    int unit = row_local & 31;
    int row_global = q * HH + (int)rank * 32 + unit;

    const float* whh = dir ? w_hh_b : w_hh_f;
    ulonglong2 wreg[16];
    {
        const ulonglong2* wp = (const ulonglong2*)(whh + row_global * HH + chunk * 64);
        #pragma unroll
        for (int i = 0; i < 16; i++) wreg[i] = wp[i];
    }

    if (t < HH) sh_h[0][t] = h0[dir * HH + t];
    float c = 0.f;
    if (w == 0) c = c0[dir * HH + (int)rank * 32 + l];

    uint32_t mb_local0 = smem_u32(&mbars[0]);
    uint32_t mb_local1 = smem_u32(&mbars[1]);
    if (t == 0) {
        asm volatile("mbarrier.init.shared.b64 [%0], 1;" :: "r"(mb_local0) : "memory");
        asm volatile("mbarrier.init.shared.b64 [%0], 1;" :: "r"(mb_local1) : "memory");
        asm volatile("mbarrier.arrive.expect_tx.shared.b64 _, [%0], %1;" :: "r"(mb_local0), "r"(TX_BYTES) : "memory");
        asm volatile("mbarrier.arrive.expect_tx.shared.b64 _, [%0], %1;" :: "r"(mb_local1), "r"(TX_BYTES) : "memory");
    }

    const float* xg = &g_xg[dir][0][0];
    int s  = dir ? (S_LEN - 1) : 0;
    int ds = dir ? -1 : 1;

    float xg0 = 0.f, xg1 = 0.f, xg2 = 0.f, xg3 = 0.f;
    if (w == 0) {
        const float* xp = xg + s * G4 + (int)rank * 32 + l;
        xg0 = xp[0]; xg1 = xp[HH]; xg2 = xp[2 * HH]; xg3 = xp[3 * HH];
    }

    uint32_t rh0[8];
    uint32_t dmb = 0;
    if (w == 0) {
        uint32_t la_h = smem_u32(&sh_h[0][(int)rank * 32 + l]);
        dmb = mb_local0 - la_h;
        #pragma unroll
        for (int p = 0; p < 8; p++)
            asm("mapa.shared::cluster.u32 %0, %1, %2;" : "=r"(rh0[p]) : "r"(la_h), "r"(p));
    }

    __syncthreads();
    asm volatile("barrier.cluster.arrive.aligned;" ::: "memory");
    asm volatile("barrier.cluster.wait.aligned;" ::: "memory");

    // warp1: lag-1 g_lstm store walk (positions s, s+ds, ...)
    float* w1_ptr = &g_lstm[s][dir * HH + (int)rank * 32 + l];
    long lstm_stride = (long)ds * (2 * HH);
    uint32_t par0 = 0, par1 = 0;
    float hn = 0.f;                    // persists; warp0's last output

    for (int step = 0; step < S_LEN; step++) {
        int buf = step & 1;
        if (step > 0) {
            if (buf) { mbar_wait_cluster(mb_local1, par1); par1 ^= 1; }
            else     { mbar_wait_cluster(mb_local0, par0); par0 ^= 1; }
        }

        // ---- stage 1: partial dot over this thread's 64 columns (f32x2) ----
        {
            const ulonglong2* hp = (const ulonglong2*)(&sh_h[buf][chunk * 64]);
            ull a0 = 0, a1 = 0, a2 = 0, a3 = 0, a4 = 0, a5 = 0, a6 = 0, a7 = 0;
            #pragma unroll
            for (int i = 0; i < 16; i += 4) {
                ulonglong2 h0v = hp[i + 0], h1v = hp[i + 1], h2v = hp[i + 2], h3v = hp[i + 3];
                a0 = fma2(wreg[i + 0].x, h0v.x, a0);
                a1 = fma2(wreg[i + 0].y, h0v.y, a1);
                a2 = fma2(wreg[i + 1].x, h1v.x, a2);
                a3 = fma2(wreg[i + 1].y, h1v.y, a3);
                a4 = fma2(wreg[i + 2].x, h2v.x, a4);
                a5 = fma2(wreg[i + 2].y, h2v.y, a5);
                a6 = fma2(wreg[i + 3].x, h3v.x, a6);
                a7 = fma2(wreg[i + 3].y, h3v.y, a7);
            }
            float r = ((sum2(a0) + sum2(a1)) + (sum2(a2) + sum2(a3)))
                    + ((sum2(a4) + sum2(a5)) + (sum2(a6) + sum2(a7)));
            sh_part[row_local][chunk] = r;
        }
        __syncthreads();   // sh_part ready; also: all warps passed this step's wait

        // re-arm this step's barrier for its next phase (step+2); off the
        // math chain. Safe: peers' next-phase st.asyncs require our current
        // broadcast below (warp0 program order) — >=1 full flight later.
        if (t == 0 && step > 0) {
            uint32_t mb = buf ? mb_local1 : mb_local0;
            asm volatile("mbarrier.arrive.expect_tx.shared.b64 _, [%0], %1;" :: "r"(mb), "r"(TX_BYTES) : "memory");
        }

        // ---- stage 2: warp0 epilogue — minimal stream, broadcast ASAP ----
        if (w == 0) {
            float4 pi = *(const float4*)&sh_part[0 * 32 + l][0];
            float4 pf = *(const float4*)&sh_part[1 * 32 + l][0];
            float4 pg = *(const float4*)&sh_part[2 * 32 + l][0];
            float4 po = *(const float4*)&sh_part[3 * 32 + l][0];

            float gi = xg0 + (pi.x + pi.y) + (pi.z + pi.w);
            float gf = xg1 + (pf.x + pf.y) + (pf.z + pf.w);
            float gg = xg2 + (pg.x + pg.y) + (pg.z + pg.w);
            float go = xg3 + (po.x + po.y) + (po.z + po.w);

            float iv = fsig(gi);
            float fv = fsig(gf);
            float gv = ftanh(gg);
            float ov = fsig(go);

            c = fv * c + iv * gv;
            hn = ov * ftanh(c);

            // broadcast h(step+1) immediately: data store carries tx signal
            uint32_t hoff = (uint32_t)(buf ^ 1) * (HH * 4);
            uint32_t moff = dmb + (uint32_t)(buf ^ 1) * 8;
            uint32_t hv = __float_as_uint(hn);
            #pragma unroll
            for (int peer = 0; peer < 8; peer++) {
                asm volatile(
                    "st.async.shared::cluster.mbarrier::complete_tx::bytes.b32 [%0], %1, [%2];"
                    :: "r"(rh0[peer] + hoff), "r"(hv), "r"(rh0[peer] + moff) : "memory");
            }

            // next-step xg prefetch; no bounds check: one-past-the-end lands
            // in the other direction's valid g_xg rows and is never consumed.
            int sn = s + ds;
            const float* xp = xg + sn * G4 + (int)rank * 32 + l;
            xg0 = xp[0]; xg1 = xp[HH]; xg2 = xp[2 * HH]; xg3 = xp[3 * HH];
        } else if (w == 1 && step > 0) {
            // lag-1 output store: sh_h[buf] = h_out(step-1), stable this phase
            w1_ptr[0] = sh_h[buf][(int)rank * 32 + l];
            w1_ptr += lstm_stride;
        }
        s += ds;
    }

    // final step's output never hits the lag path: store it directly
    if (w == 0)
        g_lstm[s - ds][dir * HH + (int)rank * 32 + l] = hn;

    asm volatile("barrier.cluster.arrive.aligned;" ::: "memory");
    asm volatile("barrier.cluster.wait.aligned;" ::: "memory");
}

// =========================================================================
// Kernel 3: emission scores (unchanged)
// =========================================================================
__global__ void frames_kernel(const float* __restrict__ W_out,
                              const float* __restrict__ b_out)
{
    __shared__ float row[512];
    int s = blockIdx.x;
    int t = threadIdx.x;
    row[t] = g_lstm[s][t];
    __syncthreads();
    int wq = t >> 5, l = t & 31;
    if (wq < T_TAGS) {
        float p = 0.f;
        #pragma unroll
        for (int i = 0; i < 16; i++)
            p += row[l + 32 * i] * W_out[wq * 512 + l + 32 * i];
        #pragma unroll
        for (int o = 16; o > 0; o >>= 1)
            p += __shfl_down_sync(0xffffffffu, p, o);
        if (l == 0) g_frames[s][wq] = p + b_out[wq];
    }
}

// =========================================================================
// CRF blocked parallel scan (R12, unchanged)
// =========================================================================
__global__ void crfA_kernel(const float* __restrict__ transitions)
{
    __shared__ float fr[CLEN][9];
    __shared__ float trs[81];
    __shared__ float M[2][9][12];
    int k = blockIdx.x, t = threadIdx.x;   // 96 threads
    for (int i = t; i < CLEN * 9; i += 96)
        fr[i / 9][i % 9] = g_frames[k * CLEN + i / 9][i % 9];
    if (t < 81) trs[t] = transitions[t];
    int e = t / 9, j = t % 9;
    bool act = (t < 81);
    if (act) M[0][e][j] = (e == j) ? 0.f : NEG_VAL;
    __syncthreads();

    float trj[9];
    if (act) {
        #pragma unroll
        for (int i = 0; i < 9; i++) trj[i] = trs[i * 9 + j];
    }
    int cur = 0;
    for (int s = 0; s < CLEN; s++) {
        if (act) {
            float v[9];
            float best = -3.4e38f;
            #pragma unroll
            for (int i = 0; i < 9; i++) {
                v[i] = M[cur][e][i] + trj[i];
                best = fmaxf(best, v[i]);
            }
            float sum = 0.f;
            #pragma unroll
            for (int i = 0; i < 9; i++) sum += __expf(v[i] - best);
            M[cur ^ 1][e][j] = best + __logf(sum) + fr[s][j];
        }
        __syncthreads();
        cur ^= 1;
    }
    if (act) g_chunkM[k][e][j] = M[cur][e][j];
}

__global__ void crfB_kernel(const float* __restrict__ transitions,
                            float* __restrict__ out)
{
    __shared__ float Ms[NCHUNK][9][9];
    __shared__ float alp[16];
    __shared__ float fin[16];
    int t = threadIdx.x;                    // 32 threads
    for (int i = t; i < NCHUNK * 81; i += 32)
        ((float*)Ms)[i] = ((const float*)g_chunkM)[i];
    if (t < 9) alp[t] = (t == START_TAG) ? 0.f : NEG_VAL;
    __syncthreads();

    if (t < 9) {
        int j = t;
        for (int k = 0; k < NCHUNK; k++) {
            g_balpha[k][j] = alp[j];
            float v[9];
            float best = -3.4e38f;
            #pragma unroll
            for (int e = 0; e < 9; e++) {
                v[e] = alp[e] + Ms[k][e][j];
                best = fmaxf(best, v[e]);
            }
            float sum = 0.f;
            #pragma unroll
            for (int e = 0; e < 9; e++) sum += __expf(v[e] - best);
            float na = best + __logf(sum);
            __syncwarp(0x1ffu);
            alp[j] = na;
            __syncwarp(0x1ffu);
        }
        fin[j] = alp[j] + transitions[j * 9 + STOP_TAG];
    }
    __syncthreads();
    if (t == 0) {
        float m = -3.4e38f; int bestj = 0;
        for (int k = 0; k < 9; k++) if (fin[k] > m) { m = fin[k]; bestj = k; }
        float sum = 0.f;
        for (int k = 0; k < 9; k++) sum += __expf(fin[k] - m);
        out[0] = m + __logf(sum);
        g_best = bestj;
    }
}

__global__ void crfC_kernel(const float* __restrict__ transitions)
{
    __shared__ float fr[CLEN][9];
    __shared__ float trs[81];
    __shared__ float alp[16];
    __shared__ unsigned char bps[CLEN][9];
    int k = blockIdx.x, t = threadIdx.x;    // 32 threads
    for (int i = t; i < CLEN * 9; i += 32)
        fr[i / 9][i % 9] = g_frames[k * CLEN + i / 9][i % 9];
    for (int i = t; i < 81; i += 32) trs[i] = transitions[i];
    if (t < 9) alp[t] = g_balpha[k][t];
    __syncthreads();

    if (t < 9) {
        int j = t;
        float trj[9];
        #pragma unroll
        for (int i = 0; i < 9; i++) trj[i] = trs[i * 9 + j];
        int base = k * CLEN;
        for (int s = 0; s < CLEN; s++) {
            float v[9];
            float best = -3.4e38f; int b = 0;
            #pragma unroll
            for (int i = 0; i < 9; i++) {
                float x = alp[i] + trj[i];
                v[i] = x;
                if (x > best) { best = x; b = i; }
            }
            float sum = 0.f;
            #pragma unroll
            for (int i = 0; i < 9; i++) sum += __expf(v[i] - best);
            float na = best + __logf(sum) + fr[s][j];
            bps[s][j] = (unsigned char)b;
            g_bp[base + s][j] = (unsigned char)b;
            __syncwarp(0x1ffu);
            alp[j] = na;
            __syncwarp(0x1ffu);
        }
    }
    __syncthreads();
    if (t < 9) {
        int tg = t;
        int smin = (k == 0) ? 1 : 0;
        for (int s = CLEN - 1; s >= smin; s--) tg = bps[s][tg];
        g_exitmap[k][t] = (unsigned char)tg;
    }
}

// merged E+F: each block composes exit-maps down to its chunk, then backtracks
__global__ void crfEF_kernel(float* __restrict__ out)
{
    __shared__ unsigned char em[NCHUNK][16];
    __shared__ unsigned char bps[CLEN][9];
    int k = blockIdx.x, t = threadIdx.x;     // 64 threads
    for (int i = t; i < NCHUNK * 9; i += 64)
        em[i / 9][i % 9] = g_exitmap[i / 9][i % 9];
    for (int i = t; i < CLEN * 9; i += 64)
        bps[i / 9][i % 9] = g_bp[k * CLEN + i / 9][i % 9];
    __syncthreads();
    if (t == 0) {
        int tg = g_best;
        for (int j = NCHUNK - 1; j > k; j--) tg = em[j][tg];
        int base = k * CLEN;
        out[base + CLEN] = (float)tg;          // out[1 + base + CLEN-1]
        int smin = (k == 0) ? 1 : 0;
        for (int s = CLEN - 1; s >= smin; s--) {
            tg = bps[s][tg];
            out[base + s] = (float)tg;         // out[1 + base + s - 1]
        }
    }
}

// =========================================================================
extern "C" void kernel_launch(void* const* d_in, const int* in_sizes, int n_in,
                              void* d_out, int out_size)
{
    const int*   sentence    = (const int*)d_in[0];
    const float* embed       = (const float*)d_in[1];
    const float* w_ih_f      = (const float*)d_in[2];
    const float* w_hh_f      = (const float*)d_in[3];
    const float* b_ih_f      = (const float*)d_in[4];
    const float* b_hh_f      = (const float*)d_in[5];
    const float* w_ih_b      = (const float*)d_in[6];
    const float* w_hh_b      = (const float*)d_in[7];
    const float* b_ih_b      = (const float*)d_in[8];
    const float* b_hh_b      = (const float*)d_in[9];
    const float* h0          = (const float*)d_in[10];
    const float* c0          = (const float*)d_in[11];
    const float* W_out       = (const float*)d_in[12];
    const float* b_out       = (const float*)d_in[13];
    const float* transitions = (const float*)d_in[14];
    float* out = (float*)d_out;

    dim3 g1(64, 32);
    xgates_kernel<<<g1, 256>>>(sentence, embed, w_ih_f, b_ih_f, b_hh_f,
                               w_ih_b, b_ih_b, b_hh_b);

    lstm_kernel<<<16, 512>>>(w_hh_f, w_hh_b, h0, c0);

    frames_kernel<<<S_LEN, 512>>>(W_out, b_out);

    crfA_kernel<<<NCHUNK, 96>>>(transitions);
    crfB_kernel<<<1, 32>>>(transitions, out);
    crfC_kernel<<<NCHUNK, 32>>>(transitions);
    crfEF_kernel<<<NCHUNK, 64>>>(out);
}

// round 16
// speedup vs baseline: 1.0824x; 1.0714x over previous
#include <cuda_runtime.h>
#include <cuda_bf16.h>
#include <cstdint>

#define S_LEN 4096
#define E_DIM 256
#define HH 256
#define G4 1024      // 4*HH
#define T_TAGS 9
#define START_TAG 7
#define STOP_TAG 8
#define NEG_VAL -10000.0f
#define NCHUNK 64
#define CLEN 64

typedef unsigned long long ull;

// ---------------- device scratch (no allocations allowed) ----------------
__device__ float g_xg[2][S_LEN][G4];     // 32 MB: precomputed x@w_ih.T + b_ih + b_hh
__device__ float g_lstm[S_LEN][2 * HH];  // 8 MB: concat(hf, hb)
__device__ float g_frames[S_LEN][T_TAGS];
__device__ float g_chunkM[NCHUNK][9][9];
__device__ float g_balpha[NCHUNK][16];
__device__ unsigned char g_bp[S_LEN][9];
__device__ unsigned char g_exitmap[NCHUNK][16];
__device__ int g_best;

// =========================================================================
// Kernel 1: x_gates GEMM with embedding gather. (R12 verbatim)
// =========================================================================
__global__ void xgates_kernel(const int* __restrict__ sentence,
                              const float* __restrict__ embed,
                              const float* __restrict__ w_ih_f,
                              const float* __restrict__ b_ih_f,
                              const float* __restrict__ b_hh_f,
                              const float* __restrict__ w_ih_b,
                              const float* __restrict__ b_ih_b,
                              const float* __restrict__ b_hh_b)
{
    __shared__ float s_x[64][65];
    __shared__ float s_w[64][65];
    __shared__ int   s_sent[64];

    int t  = threadIdx.x;            // 256 threads
    int tx = t & 15, ty = t >> 4;
    int bx = blockIdx.x;             // position tile (64 positions)
    int by = blockIdx.y;             // row tile (64 gate rows)

    if (t < 64) s_sent[t] = sentence[bx * 64 + t];
    __syncthreads();

    float acc[4][4] = {};

    for (int kc = 0; kc < 4; kc++) {
        int k0 = kc * 64;
        #pragma unroll
        for (int qq = 0; qq < 16; qq++) {
            int idx = t + 256 * qq;
            int i = idx >> 6, kk = idx & 63;
            s_x[i][kk] = embed[(long)s_sent[i] * E_DIM + k0 + kk];
        }
        #pragma unroll
        for (int qq = 0; qq < 16; qq++) {
            int idx = t + 256 * qq;
            int i = idx >> 6, kk = idx & 63;
            int R = by * 64 + i;
            const float* w = (R < 1024) ? w_ih_f : w_ih_b;
            int r = R & 1023;
            s_w[i][kk] = w[r * E_DIM + k0 + kk];
        }
        __syncthreads();
        #pragma unroll
        for (int kk = 0; kk < 64; kk++) {
            float a[4], b[4];
            #pragma unroll
            for (int i = 0; i < 4; i++) a[i] = s_w[ty * 4 + i][kk];
            #pragma unroll
            for (int j = 0; j < 4; j++) b[j] = s_x[tx * 4 + j][kk];
            #pragma unroll
            for (int i = 0; i < 4; i++)
                #pragma unroll
                for (int j = 0; j < 4; j++)
                    acc[i][j] += a[i] * b[j];
        }
        __syncthreads();
    }

    #pragma unroll
    for (int i = 0; i < 4; i++) {
        int R = by * 64 + ty * 4 + i;
        int dir = R >> 10;
        int r = R & 1023;
        float bias = dir ? (b_ih_b[r] + b_hh_b[r]) : (b_ih_f[r] + b_hh_f[r]);
        #pragma unroll
        for (int j = 0; j < 4; j++) {
            int p = bx * 64 + tx * 4 + j;
            g_xg[dir][p][r] = acc[i][j] + bias;
        }
    }
}

// ---------------- shared helpers ----------------
__device__ __forceinline__ uint32_t smem_u32(const void* p) {
    return (uint32_t)__cvta_generic_to_shared(p);
}
__device__ __forceinline__ ull fma2(ull a, ull b, ull c) {
    asm("fma.rn.f32x2 %0, %1, %2, %0;" : "+l"(c) : "l"(a), "l"(b));
    return c;
}
__device__ __forceinline__ float sum2(ull a) {
    float lo, hi;
    asm("mov.b64 {%0,%1}, %2;" : "=f"(lo), "=f"(hi) : "l"(a));
    return lo + hi;
}
__device__ __forceinline__ float fsig(float x) {
    return __fdividef(1.f, 1.f + __expf(-x));
}
__device__ __forceinline__ float ftanh(float x) {
    x = fminf(fmaxf(x, -15.f), 15.f);
    float e = __expf(2.f * x);
    return __fdividef(e - 1.f, e + 1.f);
}
__device__ __forceinline__ void mbar_wait_cluster(uint32_t mb, uint32_t parity) {
    uint32_t done;
    asm volatile(
        "{\n\t.reg .pred p;\n\t"
        "mbarrier.try_wait.parity.acquire.cluster.shared::cta.b64 p, [%1], %2;\n\t"
        "selp.b32 %0, 1, 0, p;\n\t}"
        : "=r"(done) : "r"(mb), "r"(parity) : "memory");
    if (!done) {
        asm volatile(
            "{\n\t.reg .pred P1;\n\t"
            "WL_%=:\n\t"
            "mbarrier.try_wait.parity.acquire.cluster.shared::cta.b64 P1, [%0], %1, 0x989680;\n\t"
            "@P1 bra.uni WD_%=;\n\t"
            "bra.uni WL_%=;\n\t"
            "WD_%=:\n\t}"
            :: "r"(mb), "r"(parity) : "memory");
    }
}

#define TX_BYTES 1024u  // 8 ranks * 32 units * 4 bytes per phase

// =========================================================================
// Kernel 2: serial recurrence. One 8-CTA cluster per direction.
// R12 verbatim EXCEPT: barrier re-arm moved from warp 0 (t==0) to warp 2
// (t==64), removing one predicated instruction from warp 0's stream.
// =========================================================================
__global__ void __cluster_dims__(8, 1, 1) __launch_bounds__(512, 1)
lstm_kernel(const float* __restrict__ w_hh_f,
            const float* __restrict__ w_hh_b,
            const float* __restrict__ h0,
            const float* __restrict__ c0)
{
    __shared__ __align__(16) float sh_h[2][HH];
    __shared__ __align__(16) float sh_part[128][4];   // [row_local][chunk]
    __shared__ __align__(8) ull mbars[2];

    int t = threadIdx.x;
    int w = t >> 5, l = t & 31;
    int chunk = w & 3;                         // 0..3 -> cols [chunk*64, +64)
    int row_local = ((w >> 2) << 5) + l;       // 0..127
    int dir = blockIdx.x >> 3;
    uint32_t rank;
    asm("mov.u32 %0, %%cluster_ctarank;" : "=r"(rank));
    int q = row_local >> 5;                    // gate: 0=i,1=f,2=g,3=o
    int unit = row_local & 31;
    int row_global = q * HH + (int)rank * 32 + unit;

    const float* whh = dir ? w_hh_b : w_hh_f;
    ulonglong2 wreg[16];
    {
        const ulonglong2* wp = (const ulonglong2*)(whh + row_global * HH + chunk * 64);
        #pragma unroll
        for (int i = 0; i < 16; i++) wreg[i] = wp[i];
    }

    if (t < HH) sh_h[0][t] = h0[dir * HH + t];
    float c = 0.f;
    if (w == 0) c = c0[dir * HH + (int)rank * 32 + l];

    uint32_t mb_local0 = smem_u32(&mbars[0]);
    uint32_t mb_local1 = smem_u32(&mbars[1]);
    if (t == 0) {
        asm volatile("mbarrier.init.shared.b64 [%0], 1;" :: "r"(mb_local0) : "memory");
        asm volatile("mbarrier.init.shared.b64 [%0], 1;" :: "r"(mb_local1) : "memory");
        asm volatile("mbarrier.arrive.expect_tx.shared.b64 _, [%0], %1;" :: "r"(mb_local0), "r"(TX_BYTES) : "memory");
        asm volatile("mbarrier.arrive.expect_tx.shared.b64 _, [%0], %1;" :: "r"(mb_local1), "r"(TX_BYTES) : "memory");
    }

    const float* xg = &g_xg[dir][0][0];
    int s  = dir ? (S_LEN - 1) : 0;
    int ds = dir ? -1 : 1;

    float xg0 = 0.f, xg1 = 0.f, xg2 = 0.f, xg3 = 0.f;
    if (w == 0) {
        const float* xp = xg + s * G4 + (int)rank * 32 + l;
        xg0 = xp[0]; xg1 = xp[HH]; xg2 = xp[2 * HH]; xg3 = xp[3 * HH];
    }

    uint32_t rh0[8];
    uint32_t dmb = 0;
    if (w == 0) {
        uint32_t la_h = smem_u32(&sh_h[0][(int)rank * 32 + l]);
        dmb = mb_local0 - la_h;
        #pragma unroll
        for (int p = 0; p < 8; p++)
            asm("mapa.shared::cluster.u32 %0, %1, %2;" : "=r"(rh0[p]) : "r"(la_h), "r"(p));
    }

    __syncthreads();
    asm volatile("barrier.cluster.arrive.aligned;" ::: "memory");
    asm volatile("barrier.cluster.wait.aligned;" ::: "memory");

    float* lstm_ptr = &g_lstm[s][dir * HH + (int)rank * 32 + l];
    long lstm_stride = (long)ds * (2 * HH);
    uint32_t par0 = 0, par1 = 0;

    for (int step = 0; step < S_LEN; step++) {
        int buf = step & 1;
        if (step > 0) {
            if (buf) { mbar_wait_cluster(mb_local1, par1); par1 ^= 1; }
            else     { mbar_wait_cluster(mb_local0, par0); par0 ^= 1; }
        }

        // ---- stage 1: partial dot over this thread's 64 columns (f32x2) ----
        {
            const ulonglong2* hp = (const ulonglong2*)(&sh_h[buf][chunk * 64]);
            ull a0 = 0, a1 = 0, a2 = 0, a3 = 0, a4 = 0, a5 = 0, a6 = 0, a7 = 0;
            #pragma unroll
            for (int i = 0; i < 16; i += 4) {
                ulonglong2 h0v = hp[i + 0], h1v = hp[i + 1], h2v = hp[i + 2], h3v = hp[i + 3];
                a0 = fma2(wreg[i + 0].x, h0v.x, a0);
                a1 = fma2(wreg[i + 0].y, h0v.y, a1);
                a2 = fma2(wreg[i + 1].x, h1v.x, a2);
                a3 = fma2(wreg[i + 1].y, h1v.y, a3);
                a4 = fma2(wreg[i + 2].x, h2v.x, a4);
                a5 = fma2(wreg[i + 2].y, h2v.y, a5);
                a6 = fma2(wreg[i + 3].x, h3v.x, a6);
                a7 = fma2(wreg[i + 3].y, h3v.y, a7);
            }
            float r = ((sum2(a0) + sum2(a1)) + (sum2(a2) + sum2(a3)))
                    + ((sum2(a4) + sum2(a5)) + (sum2(a6) + sum2(a7)));
            sh_part[row_local][chunk] = r;
        }
        __syncthreads();   // sh_part ready; also: all warps passed this step's wait

        // re-arm this step's barrier for its next phase (step+2); moved to
        // warp 2 lane 0 — off warp 0's serialized stream. Safe: executes
        // after the same __syncthreads; mbarrier tx accounting tolerates
        // complete_tx arriving before expect_tx within a phase.
        if (t == 64 && step > 0) {
            uint32_t mb = buf ? mb_local1 : mb_local0;
            asm volatile("mbarrier.arrive.expect_tx.shared.b64 _, [%0], %1;" :: "r"(mb), "r"(TX_BYTES) : "memory");
        }

        // ---- stage 2: warp0 epilogue — broadcast ASAP, bookkeeping after ----
        if (w == 0) {
            float4 pi = *(const float4*)&sh_part[0 * 32 + l][0];
            float4 pf = *(const float4*)&sh_part[1 * 32 + l][0];
            float4 pg = *(const float4*)&sh_part[2 * 32 + l][0];
            float4 po = *(const float4*)&sh_part[3 * 32 + l][0];

            float gi = xg0 + (pi.x + pi.y) + (pi.z + pi.w);
            float gf = xg1 + (pf.x + pf.y) + (pf.z + pf.w);
            float gg = xg2 + (pg.x + pg.y) + (pg.z + pg.w);
            float go = xg3 + (po.x + po.y) + (po.z + po.w);

            float iv = fsig(gi);
            float fv = fsig(gf);
            float gv = ftanh(gg);
            float ov = fsig(go);

            c = fv * c + iv * gv;
            float hn = ov * ftanh(c);

            // broadcast h(step+1) immediately: data store carries tx signal
            uint32_t hoff = (uint32_t)(buf ^ 1) * (HH * 4);
            uint32_t moff = dmb + (uint32_t)(buf ^ 1) * 8;
            uint32_t hv = __float_as_uint(hn);
            #pragma unroll
            for (int peer = 0; peer < 8; peer++) {
                asm volatile(
                    "st.async.shared::cluster.mbarrier::complete_tx::bytes.b32 [%0], %1, [%2];"
                    :: "r"(rh0[peer] + hoff), "r"(hv), "r"(rh0[peer] + moff) : "memory");
            }

            // off-critical-path bookkeeping: global store + next xg prefetch
            *lstm_ptr = hn;
            lstm_ptr += lstm_stride;
            int sn = s + ds;
            if (sn >= 0 && sn < S_LEN) {
                const float* xp = xg + sn * G4 + (int)rank * 32 + l;
                xg0 = xp[0]; xg1 = xp[HH]; xg2 = xp[2 * HH]; xg3 = xp[3 * HH];
            }
        }
        s += ds;
    }

    asm volatile("barrier.cluster.arrive.aligned;" ::: "memory");
    asm volatile("barrier.cluster.wait.aligned;" ::: "memory");
}

// =========================================================================
// Kernel 3: emission scores (unchanged)
// =========================================================================
__global__ void frames_kernel(const float* __restrict__ W_out,
                              const float* __restrict__ b_out)
{
    __shared__ float row[512];
    int s = blockIdx.x;
    int t = threadIdx.x;
    row[t] = g_lstm[s][t];
    __syncthreads();
    int wq = t >> 5, l = t & 31;
    if (wq < T_TAGS) {
        float p = 0.f;
        #pragma unroll
        for (int i = 0; i < 16; i++)
            p += row[l + 32 * i] * W_out[wq * 512 + l + 32 * i];
        #pragma unroll
        for (int o = 16; o > 0; o >>= 1)
            p += __shfl_down_sync(0xffffffffu, p, o);
        if (l == 0) g_frames[s][wq] = p + b_out[wq];
    }
}

// =========================================================================
// CRF blocked parallel scan (R12, unchanged)
// =========================================================================
__global__ void crfA_kernel(const float* __restrict__ transitions)
{
    __shared__ float fr[CLEN][9];
    __shared__ float trs[81];
    __shared__ float M[2][9][12];
    int k = blockIdx.x, t = threadIdx.x;   // 96 threads
    for (int i = t; i < CLEN * 9; i += 96)
        fr[i / 9][i % 9] = g_frames[k * CLEN + i / 9][i % 9];
    if (t < 81) trs[t] = transitions[t];
    int e = t / 9, j = t % 9;
    bool act = (t < 81);
    if (act) M[0][e][j] = (e == j) ? 0.f : NEG_VAL;
    __syncthreads();

    float trj[9];
    if (act) {
        #pragma unroll
        for (int i = 0; i < 9; i++) trj[i] = trs[i * 9 + j];
    }
    int cur = 0;
    for (int s = 0; s < CLEN; s++) {
        if (act) {
            float v[9];
            float best = -3.4e38f;
            #pragma unroll
            for (int i = 0; i < 9; i++) {
                v[i] = M[cur][e][i] + trj[i];
                best = fmaxf(best, v[i]);
            }
            float sum = 0.f;
            #pragma unroll
            for (int i = 0; i < 9; i++) sum += __expf(v[i] - best);
            M[cur ^ 1][e][j] = best + __logf(sum) + fr[s][j];
        }
        __syncthreads();
        cur ^= 1;
    }
    if (act) g_chunkM[k][e][j] = M[cur][e][j];
}

__global__ void crfB_kernel(const float* __restrict__ transitions,
                            float* __restrict__ out)
{
    __shared__ float Ms[NCHUNK][9][9];
    __shared__ float alp[16];
    __shared__ float fin[16];
    int t = threadIdx.x;                    // 32 threads
    for (int i = t; i < NCHUNK * 81; i += 32)
        ((float*)Ms)[i] = ((const float*)g_chunkM)[i];
    if (t < 9) alp[t] = (t == START_TAG) ? 0.f : NEG_VAL;
    __syncthreads();

    if (t < 9) {
        int j = t;
        for (int k = 0; k < NCHUNK; k++) {
            g_balpha[k][j] = alp[j];
            float v[9];
            float best = -3.4e38f;
            #pragma unroll
            for (int e = 0; e < 9; e++) {
                v[e] = alp[e] + Ms[k][e][j];
                best = fmaxf(best, v[e]);
            }
            float sum = 0.f;
            #pragma unroll
            for (int e = 0; e < 9; e++) sum += __expf(v[e] - best);
            float na = best + __logf(sum);
            __syncwarp(0x1ffu);
            alp[j] = na;
            __syncwarp(0x1ffu);
        }
        fin[j] = alp[j] + transitions[j * 9 + STOP_TAG];
    }
    __syncthreads();
    if (t == 0) {
        float m = -3.4e38f; int bestj = 0;
        for (int k = 0; k < 9; k++) if (fin[k] > m) { m = fin[k]; bestj = k; }
        float sum = 0.f;
        for (int k = 0; k < 9; k++) sum += __expf(fin[k] - m);
        out[0] = m + __logf(sum);
        g_best = bestj;
    }
}

__global__ void crfC_kernel(const float* __restrict__ transitions)
{
    __shared__ float fr[CLEN][9];
    __shared__ float trs[81];
    __shared__ float alp[16];
    __shared__ unsigned char bps[CLEN][9];
    int k = blockIdx.x, t = threadIdx.x;    // 32 threads
    for (int i = t; i < CLEN * 9; i += 32)
        fr[i / 9][i % 9] = g_frames[k * CLEN + i / 9][i % 9];
    for (int i = t; i < 81; i += 32) trs[i] = transitions[i];
    if (t < 9) alp[t] = g_balpha[k][t];
    __syncthreads();

    if (t < 9) {
        int j = t;
        float trj[9];
        #pragma unroll
        for (int i = 0; i < 9; i++) trj[i] = trs[i * 9 + j];
        int base = k * CLEN;
        for (int s = 0; s < CLEN; s++) {
            float v[9];
            float best = -3.4e38f; int b = 0;
            #pragma unroll
            for (int i = 0; i < 9; i++) {
                float x = alp[i] + trj[i];
                v[i] = x;
                if (x > best) { best = x; b = i; }
            }
            float sum = 0.f;
            #pragma unroll
            for (int i = 0; i < 9; i++) sum += __expf(v[i] - best);
            float na = best + __logf(sum) + fr[s][j];
            bps[s][j] = (unsigned char)b;
            g_bp[base + s][j] = (unsigned char)b;
            __syncwarp(0x1ffu);
            alp[j] = na;
            __syncwarp(0x1ffu);
        }
    }
    __syncthreads();
    if (t < 9) {
        int tg = t;
        int smin = (k == 0) ? 1 : 0;
        for (int s = CLEN - 1; s >= smin; s--) tg = bps[s][tg];
        g_exitmap[k][t] = (unsigned char)tg;
    }
}

// merged E+F: each block composes exit-maps down to its chunk, then backtracks
__global__ void crfEF_kernel(float* __restrict__ out)
{
    __shared__ unsigned char em[NCHUNK][16];
    __shared__ unsigned char bps[CLEN][9];
    int k = blockIdx.x, t = threadIdx.x;     // 64 threads
    for (int i = t; i < NCHUNK * 9; i += 64)
        em[i / 9][i % 9] = g_exitmap[i / 9][i % 9];
    for (int i = t; i < CLEN * 9; i += 64)
        bps[i / 9][i % 9] = g_bp[k * CLEN + i / 9][i % 9];
    __syncthreads();
    if (t == 0) {
        int tg = g_best;
        for (int j = NCHUNK - 1; j > k; j--) tg = em[j][tg];
        int base = k * CLEN;
        out[base + CLEN] = (float)tg;          // out[1 + base + CLEN-1]
        int smin = (k == 0) ? 1 : 0;
        for (int s = CLEN - 1; s >= smin; s--) {
            tg = bps[s][tg];
            out[base + s] = (float)tg;         // out[1 + base + s - 1]
        }
    }
}

// =========================================================================
extern "C" void kernel_launch(void* const* d_in, const int* in_sizes, int n_in,
                              void* d_out, int out_size)
{
    const int*   sentence    = (const int*)d_in[0];
    const float* embed       = (const float*)d_in[1];
    const float* w_ih_f      = (const float*)d_in[2];
    const float* w_hh_f      = (const float*)d_in[3];
    const float* b_ih_f      = (const float*)d_in[4];
    const float* b_hh_f      = (const float*)d_in[5];
    const float* w_ih_b      = (const float*)d_in[6];
    const float* w_hh_b      = (const float*)d_in[7];
    const float* b_ih_b      = (const float*)d_in[8];
    const float* b_hh_b      = (const float*)d_in[9];
    const float* h0          = (const float*)d_in[10];
    const float* c0          = (const float*)d_in[11];
    const float* W_out       = (const float*)d_in[12];
    const float* b_out       = (const float*)d_in[13];
    const float* transitions = (const float*)d_in[14];
    float* out = (float*)d_out;

    dim3 g1(64, 32);
    xgates_kernel<<<g1, 256>>>(sentence, embed, w_ih_f, b_ih_f, b_hh_f,
                               w_ih_b, b_ih_b, b_hh_b);

    lstm_kernel<<<16, 512>>>(w_hh_f, w_hh_b, h0, c0);

    frames_kernel<<<S_LEN, 512>>>(W_out, b_out);

    crfA_kernel<<<NCHUNK, 96>>>(transitions);
    crfB_kernel<<<1, 32>>>(transitions, out);
    crfC_kernel<<<NCHUNK, 32>>>(transitions);
    crfEF_kernel<<<NCHUNK, 64>>>(out);
}

// round 17
// speedup vs baseline: 1.0881x; 1.0053x over previous
#include <cuda_runtime.h>
#include <cuda_bf16.h>
#include <cstdint>

#define S_LEN 4096
#define E_DIM 256
#define HH 256
#define G4 1024      // 4*HH
#define T_TAGS 9
#define START_TAG 7
#define STOP_TAG 8
#define NEG_VAL -10000.0f
#define NCHUNK 64
#define CLEN 64

typedef unsigned long long ull;

// ---------------- device scratch (no allocations allowed) ----------------
__device__ float g_xg[2][S_LEN][G4];     // 32 MB: precomputed x@w_ih.T + b_ih + b_hh
__device__ float g_lstm[S_LEN][2 * HH];  // 8 MB: concat(hf, hb)
__device__ float g_frames[S_LEN][T_TAGS];
__device__ float g_chunkM[NCHUNK][9][9];
__device__ float g_balpha[NCHUNK][16];
__device__ unsigned char g_bp[S_LEN][9];
__device__ unsigned char g_exitmap[NCHUNK][16];
__device__ int g_best;

// =========================================================================
// Kernel 1: x_gates GEMM, smem transposed to [kk][row/pos] (stride 68,
// 16B-aligned): inner loop = 2x LDS.128 + 16 FFMA. Summation order == R12.
// =========================================================================
__global__ void xgates_kernel(const int* __restrict__ sentence,
                              const float* __restrict__ embed,
                              const float* __restrict__ w_ih_f,
                              const float* __restrict__ b_ih_f,
                              const float* __restrict__ b_hh_f,
                              const float* __restrict__ w_ih_b,
                              const float* __restrict__ b_ih_b,
                              const float* __restrict__ b_hh_b)
{
    __shared__ __align__(16) float s_x[64][68];   // [kk][pos]
    __shared__ __align__(16) float s_w[64][68];   // [kk][row]
    __shared__ int   s_sent[64];

    int t  = threadIdx.x;            // 256 threads
    int tx = t & 15, ty = t >> 4;
    int bx = blockIdx.x;             // position tile (64 positions)
    int by = blockIdx.y;             // row tile (64 gate rows)

    if (t < 64) s_sent[t] = sentence[bx * 64 + t];
    __syncthreads();

    float acc[4][4] = {};

    for (int kc = 0; kc < 4; kc++) {
        int k0 = kc * 64;
        #pragma unroll
        for (int qq = 0; qq < 16; qq++) {
            int idx = t + 256 * qq;
            int i = idx >> 6, kk = idx & 63;
            s_x[kk][i] = embed[(long)s_sent[i] * E_DIM + k0 + kk];
        }
        #pragma unroll
        for (int qq = 0; qq < 16; qq++) {
            int idx = t + 256 * qq;
            int i = idx >> 6, kk = idx & 63;
            int R = by * 64 + i;
            const float* w = (R < 1024) ? w_ih_f : w_ih_b;
            int r = R & 1023;
            s_w[kk][i] = w[r * E_DIM + k0 + kk];
        }
        __syncthreads();
        #pragma unroll
        for (int kk = 0; kk < 64; kk++) {
            float4 av = *(const float4*)&s_w[kk][ty * 4];
            float4 bv = *(const float4*)&s_x[kk][tx * 4];
            float a[4] = {av.x, av.y, av.z, av.w};
            float b[4] = {bv.x, bv.y, bv.z, bv.w};
            #pragma unroll
            for (int i = 0; i < 4; i++)
                #pragma unroll
                for (int j = 0; j < 4; j++)
                    acc[i][j] += a[i] * b[j];
        }
        __syncthreads();
    }

    #pragma unroll
    for (int i = 0; i < 4; i++) {
        int R = by * 64 + ty * 4 + i;
        int dir = R >> 10;
        int r = R & 1023;
        float bias = dir ? (b_ih_b[r] + b_hh_b[r]) : (b_ih_f[r] + b_hh_f[r]);
        #pragma unroll
        for (int j = 0; j < 4; j++) {
            int p = bx * 64 + tx * 4 + j;
            g_xg[dir][p][r] = acc[i][j] + bias;
        }
    }
}

// ---------------- shared helpers ----------------
__device__ __forceinline__ uint32_t smem_u32(const void* p) {
    return (uint32_t)__cvta_generic_to_shared(p);
}
__device__ __forceinline__ ull fma2(ull a, ull b, ull c) {
    asm("fma.rn.f32x2 %0, %1, %2, %0;" : "+l"(c) : "l"(a), "l"(b));
    return c;
}
__device__ __forceinline__ float sum2(ull a) {
    float lo, hi;
    asm("mov.b64 {%0,%1}, %2;" : "=f"(lo), "=f"(hi) : "l"(a));
    return lo + hi;
}
__device__ __forceinline__ float fsig(float x) {
    return __fdividef(1.f, 1.f + __expf(-x));
}
__device__ __forceinline__ float ftanh(float x) {
    x = fminf(fmaxf(x, -15.f), 15.f);
    float e = __expf(2.f * x);
    return __fdividef(e - 1.f, e + 1.f);
}
__device__ __forceinline__ void mbar_wait_cluster(uint32_t mb, uint32_t parity) {
    uint32_t done;
    asm volatile(
        "{\n\t.reg .pred p;\n\t"
        "mbarrier.try_wait.parity.acquire.cluster.shared::cta.b64 p, [%1], %2;\n\t"
        "selp.b32 %0, 1, 0, p;\n\t}"
        : "=r"(done) : "r"(mb), "r"(parity) : "memory");
    if (!done) {
        asm volatile(
            "{\n\t.reg .pred P1;\n\t"
            "WL_%=:\n\t"
            "mbarrier.try_wait.parity.acquire.cluster.shared::cta.b64 P1, [%0], %1, 0x989680;\n\t"
            "@P1 bra.uni WD_%=;\n\t"
            "bra.uni WL_%=;\n\t"
            "WD_%=:\n\t}"
            :: "r"(mb), "r"(parity) : "memory");
    }
}

#define TX_BYTES 1024u  // 8 ranks * 32 units * 4 bytes per phase

// =========================================================================
// Kernel 2: serial recurrence. One 8-CTA cluster per direction.
// (R16 verbatim: R12 loop body, re-arm on warp 2)
// =========================================================================
__global__ void __cluster_dims__(8, 1, 1) __launch_bounds__(512, 1)
lstm_kernel(const float* __restrict__ w_hh_f,
            const float* __restrict__ w_hh_b,
            const float* __restrict__ h0,
            const float* __restrict__ c0)
{
    __shared__ __align__(16) float sh_h[2][HH];
    __shared__ __align__(16) float sh_part[128][4];   // [row_local][chunk]
    __shared__ __align__(8) ull mbars[2];

    int t = threadIdx.x;
    int w = t >> 5, l = t & 31;
    int chunk = w & 3;                         // 0..3 -> cols [chunk*64, +64)
    int row_local = ((w >> 2) << 5) + l;       // 0..127
    int dir = blockIdx.x >> 3;
    uint32_t rank;
    asm("mov.u32 %0, %%cluster_ctarank;" : "=r"(rank));
    int q = row_local >> 5;                    // gate: 0=i,1=f,2=g,3=o
    int unit = row_local & 31;
    int row_global = q * HH + (int)rank * 32 + unit;

    const float* whh = dir ? w_hh_b : w_hh_f;
    ulonglong2 wreg[16];
    {
        const ulonglong2* wp = (const ulonglong2*)(whh + row_global * HH + chunk * 64);
        #pragma unroll
        for (int i = 0; i < 16; i++) wreg[i] = wp[i];
    }

    if (t < HH) sh_h[0][t] = h0[dir * HH + t];
    float c = 0.f;
    if (w == 0) c = c0[dir * HH + (int)rank * 32 + l];

    uint32_t mb_local0 = smem_u32(&mbars[0]);
    uint32_t mb_local1 = smem_u32(&mbars[1]);
    if (t == 0) {
        asm volatile("mbarrier.init.shared.b64 [%0], 1;" :: "r"(mb_local0) : "memory");
        asm volatile("mbarrier.init.shared.b64 [%0], 1;" :: "r"(mb_local1) : "memory");
        asm volatile("mbarrier.arrive.expect_tx.shared.b64 _, [%0], %1;" :: "r"(mb_local0), "r"(TX_BYTES) : "memory");
        asm volatile("mbarrier.arrive.expect_tx.shared.b64 _, [%0], %1;" :: "r"(mb_local1), "r"(TX_BYTES) : "memory");
    }

    const float* xg = &g_xg[dir][0][0];
    int s  = dir ? (S_LEN - 1) : 0;
    int ds = dir ? -1 : 1;

    float xg0 = 0.f, xg1 = 0.f, xg2 = 0.f, xg3 = 0.f;
    if (w == 0) {
        const float* xp = xg + s * G4 + (int)rank * 32 + l;
        xg0 = xp[0]; xg1 = xp[HH]; xg2 = xp[2 * HH]; xg3 = xp[3 * HH];
    }

    uint32_t rh0[8];
    uint32_t dmb = 0;
    if (w == 0) {
        uint32_t la_h = smem_u32(&sh_h[0][(int)rank * 32 + l]);
        dmb = mb_local0 - la_h;
        #pragma unroll
        for (int p = 0; p < 8; p++)
            asm("mapa.shared::cluster.u32 %0, %1, %2;" : "=r"(rh0[p]) : "r"(la_h), "r"(p));
    }

    __syncthreads();
    asm volatile("barrier.cluster.arrive.aligned;" ::: "memory");
    asm volatile("barrier.cluster.wait.aligned;" ::: "memory");

    float* lstm_ptr = &g_lstm[s][dir * HH + (int)rank * 32 + l];
    long lstm_stride = (long)ds * (2 * HH);
    uint32_t par0 = 0, par1 = 0;

    for (int step = 0; step < S_LEN; step++) {
        int buf = step & 1;
        if (step > 0) {
            if (buf) { mbar_wait_cluster(mb_local1, par1); par1 ^= 1; }
            else     { mbar_wait_cluster(mb_local0, par0); par0 ^= 1; }
        }

        // ---- stage 1: partial dot over this thread's 64 columns (f32x2) ----
        {
            const ulonglong2* hp = (const ulonglong2*)(&sh_h[buf][chunk * 64]);
            ull a0 = 0, a1 = 0, a2 = 0, a3 = 0, a4 = 0, a5 = 0, a6 = 0, a7 = 0;
            #pragma unroll
            for (int i = 0; i < 16; i += 4) {
                ulonglong2 h0v = hp[i + 0], h1v = hp[i + 1], h2v = hp[i + 2], h3v = hp[i + 3];
                a0 = fma2(wreg[i + 0].x, h0v.x, a0);
                a1 = fma2(wreg[i + 0].y, h0v.y, a1);
                a2 = fma2(wreg[i + 1].x, h1v.x, a2);
                a3 = fma2(wreg[i + 1].y, h1v.y, a3);
                a4 = fma2(wreg[i + 2].x, h2v.x, a4);
                a5 = fma2(wreg[i + 2].y, h2v.y, a5);
                a6 = fma2(wreg[i + 3].x, h3v.x, a6);
                a7 = fma2(wreg[i + 3].y, h3v.y, a7);
            }
            float r = ((sum2(a0) + sum2(a1)) + (sum2(a2) + sum2(a3)))
                    + ((sum2(a4) + sum2(a5)) + (sum2(a6) + sum2(a7)));
            sh_part[row_local][chunk] = r;
        }
        __syncthreads();   // sh_part ready; also: all warps passed this step's wait

        // re-arm this step's barrier for its next phase (step+2); on warp 2,
        // off warp 0's serialized stream. Safe: executes after the same
        // __syncthreads; mbarrier tx accounting tolerates complete_tx before
        // expect_tx within a phase.
        if (t == 64 && step > 0) {
            uint32_t mb = buf ? mb_local1 : mb_local0;
            asm volatile("mbarrier.arrive.expect_tx.shared.b64 _, [%0], %1;" :: "r"(mb), "r"(TX_BYTES) : "memory");
        }

        // ---- stage 2: warp0 epilogue — broadcast ASAP, bookkeeping after ----
        if (w == 0) {
            float4 pi = *(const float4*)&sh_part[0 * 32 + l][0];
            float4 pf = *(const float4*)&sh_part[1 * 32 + l][0];
            float4 pg = *(const float4*)&sh_part[2 * 32 + l][0];
            float4 po = *(const float4*)&sh_part[3 * 32 + l][0];

            float gi = xg0 + (pi.x + pi.y) + (pi.z + pi.w);
            float gf = xg1 + (pf.x + pf.y) + (pf.z + pf.w);
            float gg = xg2 + (pg.x + pg.y) + (pg.z + pg.w);
            float go = xg3 + (po.x + po.y) + (po.z + po.w);

            float iv = fsig(gi);
            float fv = fsig(gf);
            float gv = ftanh(gg);
            float ov = fsig(go);

            c = fv * c + iv * gv;
            float hn = ov * ftanh(c);

            // broadcast h(step+1) immediately: data store carries tx signal
            uint32_t hoff = (uint32_t)(buf ^ 1) * (HH * 4);
            uint32_t moff = dmb + (uint32_t)(buf ^ 1) * 8;
            uint32_t hv = __float_as_uint(hn);
            #pragma unroll
            for (int peer = 0; peer < 8; peer++) {
                asm volatile(
                    "st.async.shared::cluster.mbarrier::complete_tx::bytes.b32 [%0], %1, [%2];"
                    :: "r"(rh0[peer] + hoff), "r"(hv), "r"(rh0[peer] + moff) : "memory");
            }

            // off-critical-path bookkeeping: global store + next xg prefetch
            *lstm_ptr = hn;
            lstm_ptr += lstm_stride;
            int sn = s + ds;
            if (sn >= 0 && sn < S_LEN) {
                const float* xp = xg + sn * G4 + (int)rank * 32 + l;
                xg0 = xp[0]; xg1 = xp[HH]; xg2 = xp[2 * HH]; xg3 = xp[3 * HH];
            }
        }
        s += ds;
    }

    asm volatile("barrier.cluster.arrive.aligned;" ::: "memory");
    asm volatile("barrier.cluster.wait.aligned;" ::: "memory");
}

// =========================================================================
// Kernel 3: emission scores (unchanged)
// =========================================================================
__global__ void frames_kernel(const float* __restrict__ W_out,
                              const float* __restrict__ b_out)
{
    __shared__ float row[512];
    int s = blockIdx.x;
    int t = threadIdx.x;
    row[t] = g_lstm[s][t];
    __syncthreads();
    int wq = t >> 5, l = t & 31;
    if (wq < T_TAGS) {
        float p = 0.f;
        #pragma unroll
        for (int i = 0; i < 16; i++)
            p += row[l + 32 * i] * W_out[wq * 512 + l + 32 * i];
        #pragma unroll
        for (int o = 16; o > 0; o >>= 1)
            p += __shfl_down_sync(0xffffffffu, p, o);
        if (l == 0) g_frames[s][wq] = p + b_out[wq];
    }
}

// =========================================================================
// CRF blocked parallel scan (unchanged)
// =========================================================================
__global__ void crfA_kernel(const float* __restrict__ transitions)
{
    __shared__ float fr[CLEN][9];
    __shared__ float trs[81];
    __shared__ float M[2][9][12];
    int k = blockIdx.x, t = threadIdx.x;   // 96 threads
    for (int i = t; i < CLEN * 9; i += 96)
        fr[i / 9][i % 9] = g_frames[k * CLEN + i / 9][i % 9];
    if (t < 81) trs[t] = transitions[t];
    int e = t / 9, j = t % 9;
    bool act = (t < 81);
    if (act) M[0][e][j] = (e == j) ? 0.f : NEG_VAL;
    __syncthreads();

    float trj[9];
    if (act) {
        #pragma unroll
        for (int i = 0; i < 9; i++) trj[i] = trs[i * 9 + j];
    }
    int cur = 0;
    for (int s = 0; s < CLEN; s++) {
        if (act) {
            float v[9];
            float best = -3.4e38f;
            #pragma unroll
            for (int i = 0; i < 9; i++) {
                v[i] = M[cur][e][i] + trj[i];
                best = fmaxf(best, v[i]);
            }
            float sum = 0.f;
            #pragma unroll
            for (int i = 0; i < 9; i++) sum += __expf(v[i] - best);
            M[cur ^ 1][e][j] = best + __logf(sum) + fr[s][j];
        }
        __syncthreads();
        cur ^= 1;
    }
    if (act) g_chunkM[k][e][j] = M[cur][e][j];
}

__global__ void crfB_kernel(const float* __restrict__ transitions,
                            float* __restrict__ out)
{
    __shared__ float Ms[NCHUNK][9][9];
    __shared__ float alp[16];
    __shared__ float fin[16];
    int t = threadIdx.x;                    // 32 threads
    for (int i = t; i < NCHUNK * 81; i += 32)
        ((float*)Ms)[i] = ((const float*)g_chunkM)[i];
    if (t < 9) alp[t] = (t == START_TAG) ? 0.f : NEG_VAL;
    __syncthreads();

    if (t < 9) {
        int j = t;
        for (int k = 0; k < NCHUNK; k++) {
            g_balpha[k][j] = alp[j];
            float v[9];
            float best = -3.4e38f;
            #pragma unroll
            for (int e = 0; e < 9; e++) {
                v[e] = alp[e] + Ms[k][e][j];
                best = fmaxf(best, v[e]);
            }
            float sum = 0.f;
            #pragma unroll
            for (int e = 0; e < 9; e++) sum += __expf(v[e] - best);
            float na = best + __logf(sum);
            __syncwarp(0x1ffu);
            alp[j] = na;
            __syncwarp(0x1ffu);
        }
        fin[j] = alp[j] + transitions[j * 9 + STOP_TAG];
    }
    __syncthreads();
    if (t == 0) {
        float m = -3.4e38f; int bestj = 0;
        for (int k = 0; k < 9; k++) if (fin[k] > m) { m = fin[k]; bestj = k; }
        float sum = 0.f;
        for (int k = 0; k < 9; k++) sum += __expf(fin[k] - m);
        out[0] = m + __logf(sum);
        g_best = bestj;
    }
}

__global__ void crfC_kernel(const float* __restrict__ transitions)
{
    __shared__ float fr[CLEN][9];
    __shared__ float trs[81];
    __shared__ float alp[16];
    __shared__ unsigned char bps[CLEN][9];
    int k = blockIdx.x, t = threadIdx.x;    // 32 threads
    for (int i = t; i < CLEN * 9; i += 32)
        fr[i / 9][i % 9] = g_frames[k * CLEN + i / 9][i % 9];
    for (int i = t; i < 81; i += 32) trs[i] = transitions[i];
    if (t < 9) alp[t] = g_balpha[k][t];
    __syncthreads();

    if (t < 9) {
        int j = t;
        float trj[9];
        #pragma unroll
        for (int i = 0; i < 9; i++) trj[i] = trs[i * 9 + j];
        int base = k * CLEN;
        for (int s = 0; s < CLEN; s++) {
            float v[9];
            float best = -3.4e38f; int b = 0;
            #pragma unroll
            for (int i = 0; i < 9; i++) {
                float x = alp[i] + trj[i];
                v[i] = x;
                if (x > best) { best = x; b = i; }
            }
            float sum = 0.f;
            #pragma unroll
            for (int i = 0; i < 9; i++) sum += __expf(v[i] - best);
            float na = best + __logf(sum) + fr[s][j];
            bps[s][j] = (unsigned char)b;
            g_bp[base + s][j] = (unsigned char)b;
            __syncwarp(0x1ffu);
            alp[j] = na;
            __syncwarp(0x1ffu);
        }
    }
    __syncthreads();
    if (t < 9) {
        int tg = t;
        int smin = (k == 0) ? 1 : 0;
        for (int s = CLEN - 1; s >= smin; s--) tg = bps[s][tg];
        g_exitmap[k][t] = (unsigned char)tg;
    }
}

// merged E+F: each block composes exit-maps down to its chunk, then backtracks
__global__ void crfEF_kernel(float* __restrict__ out)
{
    __shared__ unsigned char em[NCHUNK][16];
    __shared__ unsigned char bps[CLEN][9];
    int k = blockIdx.x, t = threadIdx.x;     // 64 threads
    for (int i = t; i < NCHUNK * 9; i += 64)
        em[i / 9][i % 9] = g_exitmap[i / 9][i % 9];
    for (int i = t; i < CLEN * 9; i += 64)
        bps[i / 9][i % 9] = g_bp[k * CLEN + i / 9][i % 9];
    __syncthreads();
    if (t == 0) {
        int tg = g_best;
        for (int j = NCHUNK - 1; j > k; j--) tg = em[j][tg];
        int base = k * CLEN;
        out[base + CLEN] = (float)tg;          // out[1 + base + CLEN-1]
        int smin = (k == 0) ? 1 : 0;
        for (int s = CLEN - 1; s >= smin; s--) {
            tg = bps[s][tg];
            out[base + s] = (float)tg;         // out[1 + base + s - 1]
        }
    }
}

// =========================================================================
extern "C" void kernel_launch(void* const* d_in, const int* in_sizes, int n_in,
                              void* d_out, int out_size)
{
    const int*   sentence    = (const int*)d_in[0];
    const float* embed       = (const float*)d_in[1];
    const float* w_ih_f      = (const float*)d_in[2];
    const float* w_hh_f      = (const float*)d_in[3];
    const float* b_ih_f      = (const float*)d_in[4];
    const float* b_hh_f      = (const float*)d_in[5];
    const float* w_ih_b      = (const float*)d_in[6];
    const float* w_hh_b      = (const float*)d_in[7];
    const float* b_ih_b      = (const float*)d_in[8];
    const float* b_hh_b      = (const float*)d_in[9];
    const float* h0          = (const float*)d_in[10];
    const float* c0          = (const float*)d_in[11];
    const float* W_out       = (const float*)d_in[12];
    const float* b_out       = (const float*)d_in[13];
    const float* transitions = (const float*)d_in[14];
    float* out = (float*)d_out;

    dim3 g1(64, 32);
    xgates_kernel<<<g1, 256>>>(sentence, embed, w_ih_f, b_ih_f, b_hh_f,
                               w_ih_b, b_ih_b, b_hh_b);

    lstm_kernel<<<16, 512>>>(w_hh_f, w_hh_b, h0, c0);

    frames_kernel<<<S_LEN, 512>>>(W_out, b_out);

    crfA_kernel<<<NCHUNK, 96>>>(transitions);
    crfB_kernel<<<1, 32>>>(transitions, out);
    crfC_kernel<<<NCHUNK, 32>>>(transitions);
    crfEF_kernel<<<NCHUNK, 64>>>(out);
}